// round 3
// baseline (speedup 1.0000x reference)
#include <cuda_runtime.h>
#include <math.h>

#define SEQL  2048
#define BATCH 64
#define INDIM 512
#define HID   512
#define NCTA  128
#define NTHR  128
#define ROWS  16          // gate rows per CTA: 4 gates x 4 h-cols
#define PAD   516         // padded row stride (floats) -> conflict-free LDS.128

__device__ unsigned g_count;          // grid barrier arrival counter (stays 0 between runs)
__device__ volatile unsigned g_gen;   // grid barrier generation (monotonic across runs)

__device__ __forceinline__ float sigm(float x) { return 1.0f / (1.0f + __expf(-x)); }

// Accumulate a 128-wide K-quarter of the (x|h) @ W^T product.
// xb[bb] : float4* into staged activation row (b = bb*8 + bg), offset to this quarter
// wr[g]  : float4* into smem weight row (gate g of this thread's h-col), same offset
__device__ __forceinline__ void mm_accum(const float4* const xb[8],
                                         const float4* const wr[4],
                                         float acc[8][4])
{
#pragma unroll 4
    for (int kk = 0; kk < 32; ++kk) {          // 32 float4 = 128 K elements
        float4 xv[8];
#pragma unroll
        for (int bb = 0; bb < 8; ++bb) xv[bb] = xb[bb][kk];
#pragma unroll
        for (int g = 0; g < 4; ++g) {
            float4 wv = wr[g][kk];
#pragma unroll
            for (int bb = 0; bb < 8; ++bb) {
                acc[bb][g] = fmaf(xv[bb].x, wv.x, acc[bb][g]);
                acc[bb][g] = fmaf(xv[bb].y, wv.y, acc[bb][g]);
                acc[bb][g] = fmaf(xv[bb].z, wv.z, acc[bb][g]);
                acc[bb][g] = fmaf(xv[bb].w, wv.w, acc[bb][g]);
            }
        }
    }
}

__global__ void __launch_bounds__(NTHR, 1)
lstm_persistent(const float* __restrict__ input,
                const float* __restrict__ Wih,
                const float* __restrict__ Whh,
                const float* __restrict__ bih,
                const float* __restrict__ bhh,
                float* __restrict__ out)
{
    extern __shared__ float smem[];
    float* buf  = smem;                        // BATCH * PAD   (x_t, then h_{t-1})
    float* wihs = buf  + BATCH * PAD;          // ROWS * PAD
    float* whhs = wihs + ROWS * PAD;           // ROWS * PAD
    float* part = whhs + ROWS * PAD;           // 32 * NTHR     (K-split partials)
    float* bias = part + 32 * NTHR;            // ROWS

    const int tid = threadIdx.x;
    const int cta = blockIdx.x;
    const int hc0 = cta * 4;                   // first h-column owned by this CTA

    unsigned gen0 = 0;
    if (tid == 0) gen0 = g_gen;                // all CTAs read same value (no bump before all arrive)

    // ---- load this CTA's weight slices (resident for whole kernel) ----
    for (int i = tid; i < ROWS * (INDIM / 4); i += NTHR) {
        int rl = i >> 7;                       // local row 0..15  (rl = g*4 + hcl)
        int c4 = i & 127;
        int g = rl >> 2, hcl = rl & 3;
        int grow = g * HID + hc0 + hcl;        // global gate row
        ((float4*)(wihs + rl * PAD))[c4] = ((const float4*)(Wih + (size_t)grow * INDIM))[c4];
        ((float4*)(whhs + rl * PAD))[c4] = ((const float4*)(Whh + (size_t)grow * HID  ))[c4];
    }
    if (tid < ROWS) {
        int g = tid >> 2, hcl = tid & 3;
        int grow = g * HID + hc0 + hcl;
        bias[tid] = bih[grow] + bhh[grow];
    }

    // ---- thread decomposition: warp = K-quarter, lane = (bg, hcl) ----
    const int q   = tid >> 5;                  // K-quarter 0..3
    const int l   = tid & 31;
    const int bg  = l & 7;                     // batch phase: b = bb*8 + bg
    const int hcl = l >> 3;                    // local h-col 0..3
    const int hc  = hc0 + hcl;
    const int kq  = q * 32;                    // float4 offset of this quarter

    const float4* xb[8];
    const float4* wi[4];
    const float4* wh[4];
#pragma unroll
    for (int bb = 0; bb < 8; ++bb)
        xb[bb] = ((const float4*)(buf + (bb * 8 + bg) * PAD)) + kq;
#pragma unroll
    for (int g = 0; g < 4; ++g) {
        wi[g] = ((const float4*)(wihs + (g * 4 + hcl) * PAD)) + kq;
        wh[g] = ((const float4*)(whhs + (g * 4 + hcl) * PAD)) + kq;
    }

    float cst[8];
#pragma unroll
    for (int bb = 0; bb < 8; ++bb) cst[bb] = 0.0f;

    __syncthreads();                           // weights + bias ready

    for (int t = 0; t < SEQL; ++t) {
        // ---- stage x_t (independent of grid barrier -> overlaps barrier wait) ----
        {
            const float4* src = (const float4*)(input + (size_t)t * BATCH * INDIM);
            for (int i = tid; i < BATCH * INDIM / 4; i += NTHR) {
                int row = i >> 7;
                int c4  = i & 127;
                ((float4*)(buf + row * PAD))[c4] = src[i];
            }
        }
        __syncthreads();

        float acc[8][4];
#pragma unroll
        for (int bb = 0; bb < 8; ++bb)
#pragma unroll
            for (int g = 0; g < 4; ++g) acc[bb][g] = 0.0f;

        mm_accum(xb, wi, acc);                 // x_t @ W_ih^T (this quarter)

        if (t > 0) {
            // ---- grid barrier wait: all h_{t-1} writes globally visible ----
            if (tid == 0) {
                unsigned tgt = gen0 + (unsigned)t;
                while ((int)(g_gen - tgt) < 0) { }
                __threadfence();
            }
            __syncthreads();
            // ---- stage h_{t-1} (outputs buffer doubles as h history) ----
            const float4* src = (const float4*)(out + (size_t)(t - 1) * BATCH * HID);
            for (int i = tid; i < BATCH * HID / 4; i += NTHR) {
                int row = i >> 7;
                int c4  = i & 127;
                ((float4*)(buf + row * PAD))[c4] = src[i];
            }
            __syncthreads();
            mm_accum(xb, wh, acc);             // h_{t-1} @ W_hh^T (this quarter)
        }

        // ---- K-split reduction via smem ----
#pragma unroll
        for (int bb = 0; bb < 8; ++bb)
#pragma unroll
            for (int g = 0; g < 4; ++g)
                part[(bb * 4 + g) * NTHR + tid] = acc[bb][g];
        __syncthreads();

        if (tid < 32) {                        // quarter 0 owns the state update
#pragma unroll
            for (int bb = 0; bb < 8; ++bb) {
                float sv[4];
#pragma unroll
                for (int g = 0; g < 4; ++g) {
                    const float* p = part + (bb * 4 + g) * NTHR + l;
                    sv[g] = (p[0] + p[32]) + (p[64] + p[96]);
                    sv[g] += bias[g * 4 + hcl];
                }
                float ig = sigm(sv[0]);
                float fg = sigm(sv[1]);
                float gv = tanhf(sv[2]);
                float og = sigm(sv[3]);
                float cn = fmaf(fg, cst[bb], ig * gv);
                cst[bb] = cn;
                float hn = og * tanhf(cn);
                int b = bb * 8 + bg;
                out[(size_t)t * BATCH * HID + (size_t)b * HID + hc] = hn;
                if (t == SEQL - 1)             // h_n
                    out[(size_t)SEQL * BATCH * HID + (size_t)b * HID + hc] = hn;
            }
            __threadfence();                   // make h_t visible device-wide
        }
        __syncthreads();

        // ---- grid barrier arrive (release happens on 128th arrival) ----
        if (tid == 0) {
            unsigned prev = atomicAdd(&g_count, 1u);
            if (prev == NCTA - 1) {
                atomicExch(&g_count, 0u);
                __threadfence();
                g_gen = gen0 + (unsigned)(t + 1);
            }
        }
    }

    // ---- c_n ----
    if (tid < 32) {
        float* cn_out = out + (size_t)SEQL * BATCH * HID + (size_t)BATCH * HID;
#pragma unroll
        for (int bb = 0; bb < 8; ++bb) {
            int b = bb * 8 + bg;
            cn_out[(size_t)b * HID + hc] = cst[bb];
        }
    }
}

extern "C" void kernel_launch(void* const* d_in, const int* in_sizes, int n_in,
                              void* d_out, int out_size)
{
    const float* input = (const float*)d_in[0];
    const float* Wih   = (const float*)d_in[1];
    const float* Whh   = (const float*)d_in[2];
    const float* bih   = (const float*)d_in[3];
    const float* bhh   = (const float*)d_in[4];
    float* out = (float*)d_out;

    size_t smem = (size_t)(BATCH * PAD + 2 * ROWS * PAD + 32 * NTHR + ROWS) * sizeof(float);
    cudaFuncSetAttribute(lstm_persistent,
                         cudaFuncAttributeMaxDynamicSharedMemorySize, (int)smem);
    lstm_persistent<<<NCTA, NTHR, smem>>>(input, Wih, Whh, bih, bhh, out);
}

// round 4
// speedup vs baseline: 1.8151x; 1.8151x over previous
#include <cuda_runtime.h>
#include <math.h>

#define SEQL  2048
#define BATCH 64
#define INDIM 512
#define HID   512
#define NCTA  128
#define NTHR  256
#define PADX  516            // x/h buffer row stride (floats); 16B-aligned rows
#define PADW  1028           // interleaved weight row stride (floats) = 512 float2 + pad

typedef unsigned long long u64;

__device__ unsigned g_count;          // grid-barrier arrivals (returns to 0 each step)
__device__ volatile unsigned g_gen;   // grid-barrier generation (monotonic across runs)

__device__ __forceinline__ float sigm(float x){ return 1.0f/(1.0f+__expf(-x)); }

// ---- packed fp32x2 helpers (SASS FFMA2 — only reachable via PTX) ----
__device__ __forceinline__ u64 dup2(float v){
    u64 r; asm("mov.b64 %0, {%1, %2};" : "=l"(r) : "f"(v), "f"(v)); return r;
}
__device__ __forceinline__ void ffma2(u64 &d, u64 a, u64 b){
    asm("fma.rn.f32x2 %0, %1, %2, %0;" : "+l"(d) : "l"(a), "l"(b));
}
__device__ __forceinline__ float2 un2(u64 v){
    float2 f; asm("mov.b64 {%0, %1}, %2;" : "=f"(f.x), "=f"(f.y) : "l"(v)); return f;
}

// ---- cp.async helpers ----
__device__ __forceinline__ void cp16(unsigned s, const void* g){
    asm volatile("cp.async.cg.shared.global [%0], [%1], 16;" :: "r"(s), "l"(g) : "memory");
}
__device__ __forceinline__ void cp_commit(){ asm volatile("cp.async.commit_group;" ::: "memory"); }
__device__ __forceinline__ void cp_wait0(){ asm volatile("cp.async.wait_group 0;" ::: "memory"); }

// stage 64x512 fp32 (b-major) from gmem into padded smem buffer, non-blocking
__device__ __forceinline__ void stage(const float* __restrict__ g, unsigned sbase, int tid){
#pragma unroll
    for (int j = 0; j < 32; ++j){
        int i = tid + j * NTHR;
        int row = i >> 7, c4 = i & 127;
        cp16(sbase + (unsigned)(row * PADX + c4 * 4) * 4u, g + (size_t)i * 4);
    }
    cp_commit();
}

// One K-quarter (128 k) of gates += x @ W^T for 2 batches x 4 gates x (hcl pair).
// x0/x1: float4* into staged activation rows (batches b0, b0+8), offset to quarter.
// w0..w3: ulonglong2* into interleaved weight rows (gate g, this thread's hcl pair).
__device__ __forceinline__ void mm(const float4* __restrict__ x0,
                                   const float4* __restrict__ x1,
                                   const ulonglong2* __restrict__ w0,
                                   const ulonglong2* __restrict__ w1,
                                   const ulonglong2* __restrict__ w2,
                                   const ulonglong2* __restrict__ w3,
                                   u64 acc[2][4])
{
#pragma unroll 4
    for (int kk = 0; kk < 32; ++kk){
        float4 a = x0[kk];
        float4 b = x1[kk];
        u64 a0 = dup2(a.x), a1 = dup2(a.y), a2 = dup2(a.z), a3 = dup2(a.w);
        u64 b0 = dup2(b.x), b1 = dup2(b.y), b2 = dup2(b.z), b3 = dup2(b.w);
        {
            ulonglong2 p = w0[kk*2], q = w0[kk*2+1];
            ffma2(acc[0][0], a0, p.x); ffma2(acc[0][0], a1, p.y);
            ffma2(acc[0][0], a2, q.x); ffma2(acc[0][0], a3, q.y);
            ffma2(acc[1][0], b0, p.x); ffma2(acc[1][0], b1, p.y);
            ffma2(acc[1][0], b2, q.x); ffma2(acc[1][0], b3, q.y);
        }
        {
            ulonglong2 p = w1[kk*2], q = w1[kk*2+1];
            ffma2(acc[0][1], a0, p.x); ffma2(acc[0][1], a1, p.y);
            ffma2(acc[0][1], a2, q.x); ffma2(acc[0][1], a3, q.y);
            ffma2(acc[1][1], b0, p.x); ffma2(acc[1][1], b1, p.y);
            ffma2(acc[1][1], b2, q.x); ffma2(acc[1][1], b3, q.y);
        }
        {
            ulonglong2 p = w2[kk*2], q = w2[kk*2+1];
            ffma2(acc[0][2], a0, p.x); ffma2(acc[0][2], a1, p.y);
            ffma2(acc[0][2], a2, q.x); ffma2(acc[0][2], a3, q.y);
            ffma2(acc[1][2], b0, p.x); ffma2(acc[1][2], b1, p.y);
            ffma2(acc[1][2], b2, q.x); ffma2(acc[1][2], b3, q.y);
        }
        {
            ulonglong2 p = w3[kk*2], q = w3[kk*2+1];
            ffma2(acc[0][3], a0, p.x); ffma2(acc[0][3], a1, p.y);
            ffma2(acc[0][3], a2, q.x); ffma2(acc[0][3], a3, q.y);
            ffma2(acc[1][3], b0, p.x); ffma2(acc[1][3], b1, p.y);
            ffma2(acc[1][3], b2, q.x); ffma2(acc[1][3], b3, q.y);
        }
    }
}

__global__ void __launch_bounds__(NTHR, 1)
lstm_persistent(const float* __restrict__ input,
                const float* __restrict__ Wih,
                const float* __restrict__ Whh,
                const float* __restrict__ bih,
                const float* __restrict__ bhh,
                float* __restrict__ out)
{
    extern __shared__ float smem[];
    float* buf  = smem;                         // 64 * PADX   (x_t, then h_{t-1})
    float* wih  = buf  + BATCH * PADX;          // 8 * PADW    (interleaved hcl pairs)
    float* whh  = wih  + 8 * PADW;              // 8 * PADW
    float* part = whh  + 8 * PADW;              // 4 * 512 float2 = 4096 floats
    float* bias = part + 4096;                  // 16

    const int tid = threadIdx.x;
    const int cta = blockIdx.x;
    const int hc0 = cta * 4;

    unsigned gen0 = 0;
    if (tid == 0) gen0 = g_gen;

    const unsigned sbuf = (unsigned)__cvta_generic_to_shared(buf);

    // ---- interleaved weight load: row r = g*2+hp holds float2(W[g,2hp], W[g,2hp+1]) per k ----
    for (int i = tid; i < 8 * 512; i += NTHR) {
        int r = i >> 9;                          // 0..7
        int k = i & 511;
        int g = r >> 1, hp = r & 1;
        int row0 = g * HID + hc0 + hp * 2;       // global gate row (even of pair)
        ((float2*)(wih + r * PADW))[k] =
            make_float2(Wih[(size_t)row0 * INDIM + k], Wih[(size_t)(row0+1) * INDIM + k]);
        ((float2*)(whh + r * PADW))[k] =
            make_float2(Whh[(size_t)row0 * HID + k], Whh[(size_t)(row0+1) * HID + k]);
    }
    if (tid < 16) {
        int g = tid >> 2, hcl = tid & 3;
        int grow = g * HID + hc0 + hcl;
        bias[tid] = bih[grow] + bhh[grow];
    }

    // ---- decomposition: warp = (K-quarter, batch-half); lane = (hp, bsub, bg) ----
    const int q     = tid >> 6;                 // K-quarter 0..3
    const int bhalf = (tid >> 5) & 1;
    const int l     = tid & 31;
    const int bg    = l & 7;
    const int bsub  = (l >> 3) & 1;
    const int hp    = l >> 4;                   // hcl pair 0..1

    const int brow = bhalf * 32 + bsub * 16 + bg;        // batch of bb=0 (bb=1 -> +8)

    const float4* x0 = ((const float4*)(buf + brow * PADX)) + q * 32;
    const float4* x1 = x0 + (8 * PADX) / 4;
    const ulonglong2* wi0 = ((const ulonglong2*)(wih + (0*2+hp) * PADW)) + q * 64;
    const ulonglong2* wi1 = ((const ulonglong2*)(wih + (1*2+hp) * PADW)) + q * 64;
    const ulonglong2* wi2 = ((const ulonglong2*)(wih + (2*2+hp) * PADW)) + q * 64;
    const ulonglong2* wi3 = ((const ulonglong2*)(wih + (3*2+hp) * PADW)) + q * 64;
    const ulonglong2* wh0 = ((const ulonglong2*)(whh + (0*2+hp) * PADW)) + q * 64;
    const ulonglong2* wh1 = ((const ulonglong2*)(whh + (1*2+hp) * PADW)) + q * 64;
    const ulonglong2* wh2 = ((const ulonglong2*)(whh + (2*2+hp) * PADW)) + q * 64;
    const ulonglong2* wh3 = ((const ulonglong2*)(whh + (3*2+hp) * PADW)) + q * 64;

    float2* p2 = (float2*)part;

    // update-phase identity: one output (b, hcl) per thread
    const int ub   = tid >> 2;
    const int uhcl = tid & 3;
    const int uhp  = uhcl >> 1;
    const int uc   = uhcl & 1;
    const float* pbase = part + (ub * 16 + uhp * 2 + uc);   // + qq*1024 + g*4

    float cst = 0.0f;                           // c state for (ub, uhcl)

    // ---- prefetch x_0 (weights STS and cp.async ordered by first loop-top sync) ----
    stage(input, sbuf, tid);

    for (int t = 0; t < SEQL; ++t) {
        cp_wait0();
        __syncthreads();                        // x_t staged (and weights on t=0)

        u64 acc[2][4];
#pragma unroll
        for (int i = 0; i < 2; ++i)
#pragma unroll
            for (int g = 0; g < 4; ++g) acc[i][g] = 0ull;

        mm(x0, x1, wi0, wi1, wi2, wi3, acc);    // x_t @ W_ih^T (this quarter)

        if (t > 0) {
            if (tid == 0) {                     // wait for h_{t-1} global visibility
                unsigned tgt = gen0 + (unsigned)t;
                while ((int)(g_gen - tgt) < 0) { }
                __threadfence();
            }
            __syncthreads();
            stage(out + (size_t)(t - 1) * BATCH * HID, sbuf, tid);
            cp_wait0();
            __syncthreads();                    // h_{t-1} staged
            mm(x0, x1, wh0, wh1, wh2, wh3, acc);
        }

        // ---- partials: [q][b*8 + g*2 + hp] as float2 over the hcl pair ----
#pragma unroll
        for (int bb = 0; bb < 2; ++bb) {
            int b = brow + bb * 8;
#pragma unroll
            for (int g = 0; g < 4; ++g)
                p2[q * 512 + b * 8 + g * 2 + hp] = un2(acc[bb][g]);
        }
        __syncthreads();

        // ---- prefetch x_{t+1}: overlaps update + grid barrier ----
        if (t + 1 < SEQL)
            stage(input + (size_t)(t + 1) * BATCH * INDIM, sbuf, tid);

        // ---- gate update: one (b, hcl) output per thread ----
        {
            float sv[4];
#pragma unroll
            for (int g = 0; g < 4; ++g) {
                float s = bias[g * 4 + uhcl];
#pragma unroll
                for (int qq = 0; qq < 4; ++qq)
                    s += pbase[qq * 1024 + g * 4];
                sv[g] = s;
            }
            float ig = sigm(sv[0]);
            float fg = sigm(sv[1]);
            float gv = tanhf(sv[2]);
            float og = sigm(sv[3]);
            float cn = fmaf(fg, cst, ig * gv);
            cst = cn;
            float hn = og * tanhf(cn);
            out[(size_t)t * BATCH * HID + (size_t)ub * HID + hc0 + uhcl] = hn;
            if (t == SEQL - 1)
                out[(size_t)SEQL * BATCH * HID + (size_t)ub * HID + hc0 + uhcl] = hn;
        }
        __threadfence();                        // each writer makes its h_t gpu-visible
        __syncthreads();

        if (tid == 0) {                         // grid barrier arrive / release
            unsigned prev = atomicAdd(&g_count, 1u);
            if (prev == NCTA - 1) {
                atomicExch(&g_count, 0u);
                __threadfence();
                g_gen = gen0 + (unsigned)(t + 1);
            }
        }
    }

    // ---- c_n ----
    out[(size_t)SEQL * BATCH * HID + (size_t)BATCH * HID + (size_t)ub * HID + hc0 + uhcl] = cst;
}

extern "C" void kernel_launch(void* const* d_in, const int* in_sizes, int n_in,
                              void* d_out, int out_size)
{
    const float* input = (const float*)d_in[0];
    const float* Wih   = (const float*)d_in[1];
    const float* Whh   = (const float*)d_in[2];
    const float* bih   = (const float*)d_in[3];
    const float* bhh   = (const float*)d_in[4];
    float* out = (float*)d_out;

    size_t smem = (size_t)(BATCH * PADX + 2 * 8 * PADW + 4096 + 16) * sizeof(float);
    cudaFuncSetAttribute(lstm_persistent,
                         cudaFuncAttributeMaxDynamicSharedMemorySize, (int)smem);
    lstm_persistent<<<NCTA, NTHR, smem>>>(input, Wih, Whh, bih, bhh, out);
}